// round 14
// baseline (speedup 1.0000x reference)
#include <cuda_runtime.h>
#include <cuda_bf16.h>
#include <cstdint>

#define NN   100000
#define NE   640000
#define NG   2048
#define HIDD 128
#define NCLS 4

// ---------------- scratch (static device globals; no allocation) -------------
__device__ float  d_hA[(size_t)NN * HIDD];           // fp32 final activations
__device__ unsigned short d_hb16[(size_t)NN * HIDD]; // bf16 gemm output (gather src)
__device__ unsigned short d_a16[(size_t)NN * HIDD];  // bf16 aggregate output (gemm A)
__device__ uint4  d_wp[3 * 4096];   // fragment-packed W {hi.x,hi.y,lo.x,lo.y}
__device__ float  d_x3[(size_t)NN * 3];
__device__ float  d_dinv[NN];
__device__ int    d_cnt[NN];
__device__ int    d_incl[NN];
__device__ int    d_bsums[256];
__device__ int    d_rowptr[NN + 1];
__device__ int    d_fill[NN];
__device__ uint2  d_csr[NE];        // packed {src, bits(w)}
__device__ int    d_gstart[NG + 1];
__device__ int    d_ei64;
__device__ int    d_b64;

// ---------------- dtype detection --------------------------------------------
__global__ void k_detect(const int* __restrict__ ei32, const int* __restrict__ b32) {
    __shared__ int ef, bf;
    int t = threadIdx.x;
    if (t == 0) { ef = 0; bf = 0; }
    __syncthreads();
    if (t < 128) {
        if (ei32[2 * t + 1] != 0) atomicOr(&ef, 1);
        int base = (NN / 4) & ~1;
        if (b32[base + 2 * t + 1] != 0) atomicOr(&bf, 1);
    }
    __syncthreads();
    if (t == 0) { d_ei64 = ef ? 0 : 1; d_b64 = bf ? 0 : 1; }
}

__device__ __forceinline__ int idx_at(const void* p, long long i, int is64) {
    if (is64) return (int)((const long long*)p)[i];
    return ((const int*)p)[i];
}

// ---------------- bf16 helpers -------------------------------------------------
__device__ __forceinline__ void split1(float v, unsigned short& hi, unsigned short& lo) {
    __nv_bfloat16 h = __float2bfloat16(v);
    float hf = __bfloat162float(h);
    __nv_bfloat16 l = __float2bfloat16(v - hf);
    hi = *(unsigned short*)&h;
    lo = *(unsigned short*)&l;
}
__device__ __forceinline__ unsigned short f2b(float v) {
    __nv_bfloat16 h = __float2bfloat16(v);
    return *(unsigned short*)&h;
}
__device__ __forceinline__ float b2f(unsigned short u) {
    return __uint_as_float((uint32_t)u << 16);
}

// ---------------- mma.sync m16n8k16 bf16 --------------------------------------
__device__ __forceinline__ void mma16816(float* c, const uint32_t* a, uint32_t b0, uint32_t b1) {
    asm volatile(
        "mma.sync.aligned.m16n8k16.row.col.f32.bf16.bf16.f32 "
        "{%0,%1,%2,%3}, {%4,%5,%6,%7}, {%8,%9}, {%0,%1,%2,%3};"
        : "+f"(c[0]), "+f"(c[1]), "+f"(c[2]), "+f"(c[3])
        : "r"(a[0]), "r"(a[1]), "r"(a[2]), "r"(a[3]), "r"(b0), "r"(b1));
}

// ---------------- preprocessing ----------------------------------------------
__global__ void k_zero_counts() {
    int i = blockIdx.x * blockDim.x + threadIdx.x;
    if (i < NN) { d_cnt[i] = 0; d_fill[i] = 0; }
}

__global__ void k_count_deg(const void* __restrict__ ei) {
    int e = blockIdx.x * blockDim.x + threadIdx.x;
    int is64 = d_ei64;
    if (e < NE) atomicAdd(&d_cnt[idx_at(ei, (long long)NE + e, is64)], 1);
}

// warp-shuffle inclusive scan over 1024-thread blocks; also emits dinv
__global__ void k_scan_block(const int* __restrict__ in, int* __restrict__ incl,
                             int* __restrict__ bsums, int n) {
    __shared__ int wsum[32];
    int tid = threadIdx.x;
    int lane = tid & 31, wid = tid >> 5;
    int i = blockIdx.x * 1024 + tid;
    int v = (i < n) ? in[i] : 0;
    if (i < n) d_dinv[i] = rsqrtf((float)(v + 1));  // +1 self loop

    int s = v;
#pragma unroll
    for (int off = 1; off < 32; off <<= 1) {
        int t = __shfl_up_sync(0xFFFFFFFFu, s, off);
        if (lane >= off) s += t;
    }
    if (lane == 31) wsum[wid] = s;
    __syncthreads();
    if (wid == 0) {
        int w = wsum[lane];
#pragma unroll
        for (int off = 1; off < 32; off <<= 1) {
            int t = __shfl_up_sync(0xFFFFFFFFu, w, off);
            if (lane >= off) w += t;
        }
        wsum[lane] = w;
    }
    __syncthreads();
    int total = s + (wid ? wsum[wid - 1] : 0);
    if (i < n) incl[i] = total;
    if (tid == 1023) bsums[blockIdx.x] = total;
}

__global__ void k_scan_bsums(int* bsums, int nb) {
    if (threadIdx.x == 0 && blockIdx.x == 0) {
        int run = 0;
        for (int b = 0; b < nb; b++) { int t = bsums[b]; bsums[b] = run; run += t; }
    }
}

__global__ void k_scan_final(const int* __restrict__ in, const int* __restrict__ incl,
                             const int* __restrict__ bsums, int* __restrict__ out, int n) {
    int i = blockIdx.x * 1024 + threadIdx.x;
    if (i < n) {
        int off = bsums[i >> 10];
        out[i] = incl[i] - in[i] + off;
        if (i == n - 1) out[n] = incl[i] + off;
    }
}

__global__ void k_fill_csr(const void* __restrict__ ei) {
    int e = blockIdx.x * blockDim.x + threadIdx.x;
    int is64 = d_ei64;
    if (e < NE) {
        int r = idx_at(ei, e, is64);
        int c = idx_at(ei, (long long)NE + e, is64);
        int pos = d_rowptr[c] + atomicAdd(&d_fill[c], 1);
        float w = d_dinv[r];
        d_csr[pos] = make_uint2((uint32_t)r, __float_as_uint(w));
    }
}

__global__ void k_gstart(const void* __restrict__ batch) {
    int g = blockIdx.x * blockDim.x + threadIdx.x;
    if (g > NG) return;
    int is64 = d_b64;
    int lo = 0, hi = NN;
    while (lo < hi) {
        int mid = (lo + hi) >> 1;
        if (idx_at(batch, mid, is64) < g) lo = mid + 1; else hi = mid;
    }
    d_gstart[g] = lo;
}

// W2..W4 -> fragment-packed {hi,lo} uint4 (mma.sync B-frag layout)
__global__ void k_convW(const float* __restrict__ Wa, const float* __restrict__ Wb,
                        const float* __restrict__ Wc) {
    int layer = blockIdx.x;
    const float* W = (layer == 0) ? Wa : (layer == 1) ? Wb : Wc;
    uint4* pw = d_wp + layer * 4096;
    for (int idx = threadIdx.x; idx < 4096; idx += blockDim.x) {
        int lane = idx & 31;
        int nt = (idx >> 5) & 15;
        int kk = idx >> 9;
        int n = nt * 8 + (lane >> 2);
        int k0 = kk * 16 + (lane & 3) * 2;
        unsigned short h0, h1, h2, h3, l0, l1, l2, l3;
        split1(W[k0 * HIDD + n], h0, l0);
        split1(W[(k0 + 1) * HIDD + n], h1, l1);
        split1(W[(k0 + 8) * HIDD + n], h2, l2);
        split1(W[(k0 + 9) * HIDD + n], h3, l3);
        pw[idx] = make_uint4((uint32_t)h0 | ((uint32_t)h1 << 16),
                             (uint32_t)h2 | ((uint32_t)h3 << 16),
                             (uint32_t)l0 | ((uint32_t)l1 << 16),
                             (uint32_t)l2 | ((uint32_t)l3 << 16));
    }
}

// ---------------- layer 1: aggregate raw x (3 channels) -----------------------
__global__ void k_agg3(const float* __restrict__ X) {
    int n = blockIdx.x * blockDim.x + threadIdx.x;
    if (n >= NN) return;
    float dn = d_dinv[n];
    float a0 = dn * X[n * 3 + 0];
    float a1 = dn * X[n * 3 + 1];
    float a2 = dn * X[n * 3 + 2];
    int beg = d_rowptr[n], end = d_rowptr[n + 1];
    for (int e = beg; e < end; e++) {
        uint2 m = d_csr[e];
        int s = (int)m.x;
        float w = __uint_as_float(m.y);
        a0 += w * X[s * 3 + 0];
        a1 += w * X[s * 3 + 1];
        a2 += w * X[s * 3 + 2];
    }
    d_x3[n * 3 + 0] = dn * a0;
    d_x3[n * 3 + 1] = dn * a1;
    d_x3[n * 3 + 2] = dn * a2;
}

// layer 1 transform: h1 = relu(x3 @ W1 + b1) -> bf16
__global__ void k_gemm_in(const float* __restrict__ X3, const float* __restrict__ W1,
                          const float* __restrict__ b1) {
    int gw = (blockIdx.x * blockDim.x + threadIdx.x) >> 5;
    int lane = threadIdx.x & 31;
    if (gw >= NN) return;
    float x0 = X3[gw * 3 + 0], x1 = X3[gw * 3 + 1], x2 = X3[gw * 3 + 2];
    float4 w0 = *(const float4*)&W1[0 * HIDD + lane * 4];
    float4 w1 = *(const float4*)&W1[1 * HIDD + lane * 4];
    float4 w2 = *(const float4*)&W1[2 * HIDD + lane * 4];
    float4 bv = *(const float4*)&b1[lane * 4];
    ushort4 hv;
    hv.x = f2b(fmaxf(x0 * w0.x + x1 * w1.x + x2 * w2.x + bv.x, 0.0f));
    hv.y = f2b(fmaxf(x0 * w0.y + x1 * w1.y + x2 * w2.y + bv.y, 0.0f));
    hv.z = f2b(fmaxf(x0 * w0.z + x1 * w1.z + x2 * w2.z + bv.z, 0.0f));
    hv.w = f2b(fmaxf(x0 * w0.w + x1 * w1.w + x2 * w2.w + bv.w, 0.0f));
    *(ushort4*)&d_a16[(size_t)gw * HIDD + lane * 4] = hv;
}

// ---------------- HMMA GEMM: 2D warp tiling (4M x 2N), smem A + packed W -------
// 256 thr (8 warps), block tile 128 rows x 128 cols.
// warp (wm, wn): rows wm*32..+31 (2 m-tiles), cols wn*64..+63 (8 n-tiles).
// Each warp reads only HALF of W (32KB) -> block W-LDS traffic 256KB (was 512).
#define HGA_STRIDE 136
#define HG_SMEM (65536 + 128 * HGA_STRIDE * 2)   // 100352 B

__global__ void __launch_bounds__(256, 2)
k_hgemm(const unsigned short* __restrict__ A16,
        const uint4* __restrict__ WP,
        unsigned short* __restrict__ Y) {
    extern __shared__ char smraw[];
    uint4* sW = (uint4*)smraw;                               // [4096]
    unsigned short* sA = (unsigned short*)(smraw + 65536);   // [128][136]

    int tid = threadIdx.x;
    int rb = blockIdx.x * 128;

    // stage W (coalesced LDG.128)
    for (int i = tid; i < 4096; i += 256) sW[i] = WP[i];
    // stage A: 128 rows x 256B, 16B per op
    for (int i = tid; i < 128 * 16; i += 256) {
        int r = i >> 4, seg = i & 15;
        uint4 v = make_uint4(0u, 0u, 0u, 0u);
        if (rb + r < NN) v = *(const uint4*)&A16[(size_t)(rb + r) * HIDD + seg * 8];
        *(uint4*)&sA[r * HGA_STRIDE + seg * 8] = v;
    }
    __syncthreads();

    int warp = tid >> 5, lane = tid & 31;
    int wm = warp & 3;            // M group: rows wm*32..+31
    int wn = warp >> 2;           // N half: cols wn*64..+63
    int tr0 = wm * 32 + (lane >> 2);   // m-tile 0: rows tr0, tr0+8
    int tr1 = tr0 + 16;                // m-tile 1: rows tr1, tr1+8
    int kbase = (lane & 3) * 2;

    float acc[2][8][4];
#pragma unroll
    for (int mt = 0; mt < 2; mt++)
#pragma unroll
        for (int nt = 0; nt < 8; nt++)
#pragma unroll
            for (int j = 0; j < 4; j++) acc[mt][nt][j] = 0.0f;

#pragma unroll
    for (int kk = 0; kk < 8; kk++) {
        int kc = kk * 16 + kbase;
        uint32_t a0[4], a1[4];
        a0[0] = *(const uint32_t*)&sA[tr0 * HGA_STRIDE + kc];
        a0[1] = *(const uint32_t*)&sA[(tr0 + 8) * HGA_STRIDE + kc];
        a0[2] = *(const uint32_t*)&sA[tr0 * HGA_STRIDE + kc + 8];
        a0[3] = *(const uint32_t*)&sA[(tr0 + 8) * HGA_STRIDE + kc + 8];
        a1[0] = *(const uint32_t*)&sA[tr1 * HGA_STRIDE + kc];
        a1[1] = *(const uint32_t*)&sA[(tr1 + 8) * HGA_STRIDE + kc];
        a1[2] = *(const uint32_t*)&sA[tr1 * HGA_STRIDE + kc + 8];
        a1[3] = *(const uint32_t*)&sA[(tr1 + 8) * HGA_STRIDE + kc + 8];
        const uint4* bp = &sW[kk * 512 + wn * 256 + lane];
#pragma unroll
        for (int nt = 0; nt < 8; nt++) {
            uint4 w = bp[nt * 32];
            mma16816(acc[0][nt], a0, w.x, w.y);
            mma16816(acc[0][nt], a0, w.z, w.w);
            mma16816(acc[1][nt], a1, w.x, w.y);
            mma16816(acc[1][nt], a1, w.z, w.w);
        }
    }

#pragma unroll
    for (int mt = 0; mt < 2; mt++) {
        int row0 = rb + tr0 + mt * 16;
        int row1 = row0 + 8;
#pragma unroll
        for (int nt = 0; nt < 8; nt++) {
            int col = wn * 64 + nt * 8 + kbase;
            if (row0 < NN) {
                __nv_bfloat162 v = __floats2bfloat162_rn(acc[mt][nt][0], acc[mt][nt][1]);
                *(__nv_bfloat162*)&Y[(size_t)row0 * HIDD + col] = v;
            }
            if (row1 < NN) {
                __nv_bfloat162 v = __floats2bfloat162_rn(acc[mt][nt][2], acc[mt][nt][3]);
                *(__nv_bfloat162*)&Y[(size_t)row1 * HIDD + col] = v;
            }
        }
    }
}

// ---------------- aggregation (bf16 gather, 128 channels) ----------------------
// out[n] = relu(dinv[n]*(sum_e w_e*h[src] + dinv[n]*h[n]) + b), h stored bf16
template <int SPLIT>
__global__ void k_aggregate(const unsigned short* __restrict__ Hin,
                            const float* __restrict__ bias,
                            float* __restrict__ Hout, int nlimit) {
    int warp = (blockIdx.x * blockDim.x + threadIdx.x) >> 5;
    int lane = threadIdx.x & 31;
    if (warp >= nlimit) return;
    int n = warp;
    int c = lane * 4;
    float dn = d_dinv[n];

    ushort4 hv = *(const ushort4*)&Hin[(size_t)n * HIDD + c];
    float4 acc = make_float4(dn * b2f(hv.x), dn * b2f(hv.y),
                             dn * b2f(hv.z), dn * b2f(hv.w));

    int beg = d_rowptr[n], end = d_rowptr[n + 1];
    int e = beg;
    for (; e + 4 <= end; e += 4) {
        uint2 m0 = d_csr[e],     m1 = d_csr[e + 1];
        uint2 m2 = d_csr[e + 2], m3 = d_csr[e + 3];
        float w0 = __uint_as_float(m0.y), w1 = __uint_as_float(m1.y);
        float w2 = __uint_as_float(m2.y), w3 = __uint_as_float(m3.y);
        ushort4 h0 = *(const ushort4*)&Hin[(size_t)m0.x * HIDD + c];
        ushort4 h1 = *(const ushort4*)&Hin[(size_t)m1.x * HIDD + c];
        ushort4 h2 = *(const ushort4*)&Hin[(size_t)m2.x * HIDD + c];
        ushort4 h3 = *(const ushort4*)&Hin[(size_t)m3.x * HIDD + c];
        acc.x += w0 * b2f(h0.x) + w1 * b2f(h1.x) + w2 * b2f(h2.x) + w3 * b2f(h3.x);
        acc.y += w0 * b2f(h0.y) + w1 * b2f(h1.y) + w2 * b2f(h2.y) + w3 * b2f(h3.y);
        acc.z += w0 * b2f(h0.z) + w1 * b2f(h1.z) + w2 * b2f(h2.z) + w3 * b2f(h3.z);
        acc.w += w0 * b2f(h0.w) + w1 * b2f(h1.w) + w2 * b2f(h2.w) + w3 * b2f(h3.w);
    }
    for (; e < end; e++) {
        uint2 m = d_csr[e];
        float w = __uint_as_float(m.y);
        ushort4 hs = *(const ushort4*)&Hin[(size_t)m.x * HIDD + c];
        acc.x += w * b2f(hs.x); acc.y += w * b2f(hs.y);
        acc.z += w * b2f(hs.z); acc.w += w * b2f(hs.w);
    }

    float4 bv = *(const float4*)&bias[c];
    float y[4];
    y[0] = fmaxf(dn * acc.x + bv.x, 0.0f);
    y[1] = fmaxf(dn * acc.y + bv.y, 0.0f);
    y[2] = fmaxf(dn * acc.z + bv.z, 0.0f);
    y[3] = fmaxf(dn * acc.w + bv.w, 0.0f);

    if (SPLIT) {
        ushort4 hs4;
        hs4.x = f2b(y[0]); hs4.y = f2b(y[1]);
        hs4.z = f2b(y[2]); hs4.w = f2b(y[3]);
        *(ushort4*)&d_a16[(size_t)n * HIDD + c] = hs4;
    } else {
        *(float4*)&Hout[(size_t)n * HIDD + c] = make_float4(y[0], y[1], y[2], y[3]);
    }
}

// ---------------- mean pool + FC ---------------------------------------------
__global__ void k_pool_fc(const float* __restrict__ H, const float* __restrict__ Wfc,
                          const float* __restrict__ bfc, float* __restrict__ out) {
    int g = blockIdx.x;
    int j = threadIdx.x;
    int beg = d_gstart[g], end = d_gstart[g + 1];
    float s = 0.0f;
    for (int r = beg; r < end; r++) s += H[(size_t)r * HIDD + j];
    float cntf = fmaxf((float)(end - beg), 1.0f);
    __shared__ float smem[HIDD];
    smem[j] = s / cntf;
    __syncthreads();
    if (j < NCLS) {
        float a = bfc[j];
        for (int k = 0; k < HIDD; k++) a += smem[k] * Wfc[k * NCLS + j];
        out[g * NCLS + j] = a;
    }
}

// ---------------- launch ------------------------------------------------------
extern "C" void kernel_launch(void* const* d_in, const int* in_sizes, int n_in,
                              void* d_out, int out_size) {
    const float* x     = (const float*)d_in[0];
    const void*  ei    = d_in[1];
    const void*  batch = d_in[2];
    const float* W1 = (const float*)d_in[3];  const float* b1 = (const float*)d_in[4];
    const float* W2 = (const float*)d_in[5];  const float* b2 = (const float*)d_in[6];
    const float* W3 = (const float*)d_in[7];  const float* b3 = (const float*)d_in[8];
    const float* W4 = (const float*)d_in[9];  const float* b4 = (const float*)d_in[10];
    const float* Wfc = (const float*)d_in[11]; const float* bfc = (const float*)d_in[12];
    float* out = (float*)d_out;

    cudaFuncSetAttribute(k_hgemm, cudaFuncAttributeMaxDynamicSharedMemorySize, HG_SMEM);

    void* p;
    cudaGetSymbolAddress(&p, d_hA);     float* hA = (float*)p;
    cudaGetSymbolAddress(&p, d_hb16);   unsigned short* hb16 = (unsigned short*)p;
    cudaGetSymbolAddress(&p, d_a16);    unsigned short* a16 = (unsigned short*)p;
    cudaGetSymbolAddress(&p, d_x3);     float* x3 = (float*)p;
    cudaGetSymbolAddress(&p, d_cnt);    int* cnt = (int*)p;
    cudaGetSymbolAddress(&p, d_incl);   int* incl = (int*)p;
    cudaGetSymbolAddress(&p, d_bsums);  int* bsums = (int*)p;
    cudaGetSymbolAddress(&p, d_rowptr); int* rowptr = (int*)p;
    cudaGetSymbolAddress(&p, d_wp);     uint4* wp = (uint4*)p;

    const int TPB = 256;
    int gN  = (NN + TPB - 1) / TPB;
    int gE  = (NE + TPB - 1) / TPB;
    int gW  = (NN * 32 + TPB - 1) / TPB;
    int nbN = (NN + 1023) / 1024;
    int gG  = (NG + 1 + TPB - 1) / TPB;
    int nT  = (NN + 127) / 128;

    // preprocessing
    k_detect<<<1, 256>>>((const int*)ei, (const int*)batch);
    k_zero_counts<<<gN, TPB>>>();
    k_count_deg<<<gE, TPB>>>(ei);
    k_scan_block<<<nbN, 1024>>>(cnt, incl, bsums, NN);
    k_scan_bsums<<<1, 32>>>(bsums, nbN);
    k_scan_final<<<nbN, 1024>>>(cnt, incl, bsums, rowptr, NN);
    k_fill_csr<<<gE, TPB>>>(ei);
    k_gstart<<<gG, TPB>>>(batch);
    k_convW<<<3, 256>>>(W2, W3, W4);

    // layer 1
    k_agg3<<<gN, TPB>>>(x);
    k_gemm_in<<<gW, TPB>>>(x3, W1, b1);

    // layers 2-4: HMMA gemm (2D warp tiling) then aggregate
    k_hgemm<<<nT, 256, HG_SMEM>>>(a16, wp, hb16);
    k_aggregate<1><<<gW, TPB>>>(hb16, b2, nullptr, NN);
    k_hgemm<<<nT, 256, HG_SMEM>>>(a16, wp + 4096, hb16);
    k_aggregate<1><<<gW, TPB>>>(hb16, b3, nullptr, NN);
    k_hgemm<<<nT, 256, HG_SMEM>>>(a16, wp + 2 * 4096, hb16);
    k_aggregate<0><<<gW, TPB>>>(hb16, b4, hA, NN);

    // pool + fc
    k_pool_fc<<<NG, HIDD>>>(hA, Wfc, bfc, out);
}

// round 15
// speedup vs baseline: 1.2102x; 1.2102x over previous
#include <cuda_runtime.h>
#include <cuda_bf16.h>
#include <cstdint>

#define NN   100000
#define NE   640000
#define NG   2048
#define HIDD 128
#define NCLS 4

// ---------------- scratch (static device globals; no allocation) -------------
__device__ unsigned short d_hb16[(size_t)NN * HIDD]; // bf16 gemm output (gather src)
__device__ unsigned short d_a16[(size_t)NN * HIDD];  // bf16 aggregate output (gemm A / pool src)
__device__ uint4  d_wp[3 * 4096];   // fragment-packed W {hi.x,hi.y,lo.x,lo.y}
__device__ float  d_dinv[NN];
__device__ int    d_cnt[NN];
__device__ int    d_incl[NN];
__device__ int    d_bsums[256];
__device__ int    d_rowptr[NN + 1];
__device__ int    d_fill[NN];
__device__ uint2  d_csr[NE];        // packed {src, bits(w)}
__device__ int    d_gstart[NG + 1];
__device__ int    d_ei64;
__device__ int    d_b64;

// ---------------- helpers ------------------------------------------------------
__device__ __forceinline__ int idx_at(const void* p, long long i, int is64) {
    if (is64) return (int)((const long long*)p)[i];
    return ((const int*)p)[i];
}
__device__ __forceinline__ void split1(float v, unsigned short& hi, unsigned short& lo) {
    __nv_bfloat16 h = __float2bfloat16(v);
    float hf = __bfloat162float(h);
    __nv_bfloat16 l = __float2bfloat16(v - hf);
    hi = *(unsigned short*)&h;
    lo = *(unsigned short*)&l;
}
__device__ __forceinline__ unsigned short f2b(float v) {
    __nv_bfloat16 h = __float2bfloat16(v);
    return *(unsigned short*)&h;
}
__device__ __forceinline__ float b2f(unsigned short u) {
    return __uint_as_float((uint32_t)u << 16);
}
__device__ __forceinline__ uint32_t cvta_s(const void* p) {
    uint32_t a;
    asm("{ .reg .u64 t; cvta.to.shared.u64 t, %1; cvt.u32.u64 %0, t; }" : "=r"(a) : "l"(p));
    return a;
}
#define CP16(dst, src)      asm volatile("cp.async.cg.shared.global [%0], [%1], 16;" :: "r"(dst), "l"(src))
#define CP16Z(dst, src, sz) asm volatile("cp.async.cg.shared.global [%0], [%1], 16, %2;" :: "r"(dst), "l"(src), "r"(sz))
#define CPCOMMIT()          asm volatile("cp.async.commit_group;" ::: "memory")
#define CPWAIT()            asm volatile("cp.async.wait_group 0;" ::: "memory")

__device__ __forceinline__ void mma16816(float* c, const uint32_t* a, uint32_t b0, uint32_t b1) {
    asm volatile(
        "mma.sync.aligned.m16n8k16.row.col.f32.bf16.bf16.f32 "
        "{%0,%1,%2,%3}, {%4,%5,%6,%7}, {%8,%9}, {%0,%1,%2,%3};"
        : "+f"(c[0]), "+f"(c[1]), "+f"(c[2]), "+f"(c[3])
        : "r"(a[0]), "r"(a[1]), "r"(a[2]), "r"(a[3]), "r"(b0), "r"(b1));
}

// ---------------- preprocessing ----------------------------------------------
// fused: zero counts + dtype detection (block 0)
__global__ void k_zero_detect(const int* __restrict__ ei32, const int* __restrict__ b32) {
    int i = blockIdx.x * blockDim.x + threadIdx.x;
    if (i < NN) { d_cnt[i] = 0; d_fill[i] = 0; }
    if (blockIdx.x == 0) {
        __shared__ int ef, bf;
        int t = threadIdx.x;
        if (t == 0) { ef = 0; bf = 0; }
        __syncthreads();
        if (t < 128) {
            if (ei32[2 * t + 1] != 0) atomicOr(&ef, 1);
            int base = (NN / 4) & ~1;
            if (b32[base + 2 * t + 1] != 0) atomicOr(&bf, 1);
        }
        __syncthreads();
        if (t == 0) { d_ei64 = ef ? 0 : 1; d_b64 = bf ? 0 : 1; }
    }
}

__global__ void k_count_deg(const void* __restrict__ ei) {
    int e = blockIdx.x * blockDim.x + threadIdx.x;
    int is64 = d_ei64;
    if (e < NE) atomicAdd(&d_cnt[idx_at(ei, (long long)NE + e, is64)], 1);
}

// warp-shuffle inclusive scan over 1024-thread blocks; also emits dinv
__global__ void k_scan_block(const int* __restrict__ in, int* __restrict__ incl,
                             int* __restrict__ bsums, int n) {
    __shared__ int wsum[32];
    int tid = threadIdx.x;
    int lane = tid & 31, wid = tid >> 5;
    int i = blockIdx.x * 1024 + tid;
    int v = (i < n) ? in[i] : 0;
    if (i < n) d_dinv[i] = rsqrtf((float)(v + 1));  // +1 self loop

    int s = v;
#pragma unroll
    for (int off = 1; off < 32; off <<= 1) {
        int t = __shfl_up_sync(0xFFFFFFFFu, s, off);
        if (lane >= off) s += t;
    }
    if (lane == 31) wsum[wid] = s;
    __syncthreads();
    if (wid == 0) {
        int w = wsum[lane];
#pragma unroll
        for (int off = 1; off < 32; off <<= 1) {
            int t = __shfl_up_sync(0xFFFFFFFFu, w, off);
            if (lane >= off) w += t;
        }
        wsum[lane] = w;
    }
    __syncthreads();
    int total = s + (wid ? wsum[wid - 1] : 0);
    if (i < n) incl[i] = total;
    if (tid == 1023) bsums[blockIdx.x] = total;
}

__global__ void k_scan_bsums(int* bsums, int nb) {
    if (threadIdx.x == 0 && blockIdx.x == 0) {
        int run = 0;
        for (int b = 0; b < nb; b++) { int t = bsums[b]; bsums[b] = run; run += t; }
    }
}

__global__ void k_scan_final(const int* __restrict__ in, const int* __restrict__ incl,
                             const int* __restrict__ bsums, int* __restrict__ out, int n) {
    int i = blockIdx.x * 1024 + threadIdx.x;
    if (i < n) {
        int off = bsums[i >> 10];
        out[i] = incl[i] - in[i] + off;
        if (i == n - 1) out[n] = incl[i] + off;
    }
}

__global__ void k_fill_csr(const void* __restrict__ ei) {
    int e = blockIdx.x * blockDim.x + threadIdx.x;
    int is64 = d_ei64;
    if (e < NE) {
        int r = idx_at(ei, e, is64);
        int c = idx_at(ei, (long long)NE + e, is64);
        int pos = d_rowptr[c] + atomicAdd(&d_fill[c], 1);
        float w = d_dinv[r];
        d_csr[pos] = make_uint2((uint32_t)r, __float_as_uint(w));
    }
}

// fused: blocks 0..2 -> convW (W2..W4 fragment-pack); blocks 3.. -> gstart
__global__ void k_gstart_convW(const void* __restrict__ batch,
                               const float* __restrict__ Wa, const float* __restrict__ Wb,
                               const float* __restrict__ Wc) {
    if (blockIdx.x < 3) {
        int layer = blockIdx.x;
        const float* W = (layer == 0) ? Wa : (layer == 1) ? Wb : Wc;
        uint4* pw = d_wp + layer * 4096;
        for (int idx = threadIdx.x; idx < 4096; idx += blockDim.x) {
            int lane = idx & 31;
            int nt = (idx >> 5) & 15;
            int kk = idx >> 9;
            int n = nt * 8 + (lane >> 2);
            int k0 = kk * 16 + (lane & 3) * 2;
            unsigned short h0, h1, h2, h3, l0, l1, l2, l3;
            split1(W[k0 * HIDD + n], h0, l0);
            split1(W[(k0 + 1) * HIDD + n], h1, l1);
            split1(W[(k0 + 8) * HIDD + n], h2, l2);
            split1(W[(k0 + 9) * HIDD + n], h3, l3);
            pw[idx] = make_uint4((uint32_t)h0 | ((uint32_t)h1 << 16),
                                 (uint32_t)h2 | ((uint32_t)h3 << 16),
                                 (uint32_t)l0 | ((uint32_t)l1 << 16),
                                 (uint32_t)l2 | ((uint32_t)l3 << 16));
        }
    } else {
        int g = (blockIdx.x - 3) * blockDim.x + threadIdx.x;
        if (g > NG) return;
        int is64 = d_b64;
        int lo = 0, hi = NN;
        while (lo < hi) {
            int mid = (lo + hi) >> 1;
            if (idx_at(batch, mid, is64) < g) lo = mid + 1; else hi = mid;
        }
        d_gstart[g] = lo;
    }
}

// ---------------- layer 1 fused: aggregate x (3ch) + transform + relu -> a16 ---
// warp per node: lanes split the edge list, 3-channel warp reduction, then
// each lane emits its 4 output channels of relu(x3 @ W1 + b1).
__global__ void k_layer1(const float* __restrict__ X, const float* __restrict__ W1,
                         const float* __restrict__ b1) {
    int n = (blockIdx.x * blockDim.x + threadIdx.x) >> 5;
    int lane = threadIdx.x & 31;
    if (n >= NN) return;
    float dn = d_dinv[n];

    int beg = d_rowptr[n], end = d_rowptr[n + 1];
    float a0 = 0.f, a1 = 0.f, a2 = 0.f;
    for (int e = beg + lane; e < end; e += 32) {
        uint2 m = d_csr[e];
        int s = (int)m.x;
        float w = __uint_as_float(m.y);
        a0 += w * X[s * 3 + 0];
        a1 += w * X[s * 3 + 1];
        a2 += w * X[s * 3 + 2];
    }
#pragma unroll
    for (int off = 16; off > 0; off >>= 1) {
        a0 += __shfl_down_sync(0xFFFFFFFFu, a0, off);
        a1 += __shfl_down_sync(0xFFFFFFFFu, a1, off);
        a2 += __shfl_down_sync(0xFFFFFFFFu, a2, off);
    }
    a0 = __shfl_sync(0xFFFFFFFFu, a0, 0);
    a1 = __shfl_sync(0xFFFFFFFFu, a1, 0);
    a2 = __shfl_sync(0xFFFFFFFFu, a2, 0);

    float x0 = dn * (a0 + dn * X[n * 3 + 0]);
    float x1 = dn * (a1 + dn * X[n * 3 + 1]);
    float x2 = dn * (a2 + dn * X[n * 3 + 2]);

    float4 w0 = *(const float4*)&W1[0 * HIDD + lane * 4];
    float4 w1 = *(const float4*)&W1[1 * HIDD + lane * 4];
    float4 w2 = *(const float4*)&W1[2 * HIDD + lane * 4];
    float4 bv = *(const float4*)&b1[lane * 4];
    ushort4 hv;
    hv.x = f2b(fmaxf(x0 * w0.x + x1 * w1.x + x2 * w2.x + bv.x, 0.0f));
    hv.y = f2b(fmaxf(x0 * w0.y + x1 * w1.y + x2 * w2.y + bv.y, 0.0f));
    hv.z = f2b(fmaxf(x0 * w0.z + x1 * w1.z + x2 * w2.z + bv.z, 0.0f));
    hv.w = f2b(fmaxf(x0 * w0.w + x1 * w1.w + x2 * w2.w + bv.w, 0.0f));
    *(ushort4*)&d_a16[(size_t)n * HIDD + lane * 4] = hv;
}

// ---------------- HMMA GEMM: cp.async staged A + packed W, 2D warp tiling ------
#define HGA_STRIDE 136
#define HG_SMEM (65536 + 128 * HGA_STRIDE * 2)   // 100352 B

__global__ void __launch_bounds__(256, 2)
k_hgemm(const unsigned short* __restrict__ A16,
        const uint4* __restrict__ WP,
        unsigned short* __restrict__ Y) {
    extern __shared__ char smraw[];
    uint4* sW = (uint4*)smraw;                               // [4096]
    unsigned short* sA = (unsigned short*)(smraw + 65536);   // [128][136]

    int tid = threadIdx.x;
    int rb = blockIdx.x * 128;
    uint32_t sWa = cvta_s(sW);
    uint32_t sAa = cvta_s(sA);

    // stage W + A via cp.async (16B ops)
    for (int i = tid; i < 4096; i += 256)
        CP16(sWa + i * 16, &WP[i]);
    for (int i = tid; i < 128 * 16; i += 256) {
        int r = i >> 4, seg = i & 15;
        int gr = rb + r;
        const unsigned short* src = &A16[(size_t)min(gr, NN - 1) * HIDD + seg * 8];
        uint32_t sz = (gr < NN) ? 16u : 0u;
        CP16Z(sAa + (r * HGA_STRIDE + seg * 8) * 2, src, sz);
    }
    CPCOMMIT();
    CPWAIT();
    __syncthreads();

    int warp = tid >> 5, lane = tid & 31;
    int wm = warp & 3;
    int wn = warp >> 2;
    int tr0 = wm * 32 + (lane >> 2);
    int tr1 = tr0 + 16;
    int kbase = (lane & 3) * 2;

    float acc[2][8][4];
#pragma unroll
    for (int mt = 0; mt < 2; mt++)
#pragma unroll
        for (int nt = 0; nt < 8; nt++)
#pragma unroll
            for (int j = 0; j < 4; j++) acc[mt][nt][j] = 0.0f;

#pragma unroll
    for (int kk = 0; kk < 8; kk++) {
        int kc = kk * 16 + kbase;
        uint32_t a0[4], a1[4];
        a0[0] = *(const uint32_t*)&sA[tr0 * HGA_STRIDE + kc];
        a0[1] = *(const uint32_t*)&sA[(tr0 + 8) * HGA_STRIDE + kc];
        a0[2] = *(const uint32_t*)&sA[tr0 * HGA_STRIDE + kc + 8];
        a0[3] = *(const uint32_t*)&sA[(tr0 + 8) * HGA_STRIDE + kc + 8];
        a1[0] = *(const uint32_t*)&sA[tr1 * HGA_STRIDE + kc];
        a1[1] = *(const uint32_t*)&sA[(tr1 + 8) * HGA_STRIDE + kc];
        a1[2] = *(const uint32_t*)&sA[tr1 * HGA_STRIDE + kc + 8];
        a1[3] = *(const uint32_t*)&sA[(tr1 + 8) * HGA_STRIDE + kc + 8];
        const uint4* bp = &sW[kk * 512 + wn * 256 + lane];
#pragma unroll
        for (int nt = 0; nt < 8; nt++) {
            uint4 w = bp[nt * 32];
            mma16816(acc[0][nt], a0, w.x, w.y);
            mma16816(acc[0][nt], a0, w.z, w.w);
            mma16816(acc[1][nt], a1, w.x, w.y);
            mma16816(acc[1][nt], a1, w.z, w.w);
        }
    }

#pragma unroll
    for (int mt = 0; mt < 2; mt++) {
        int row0 = rb + tr0 + mt * 16;
        int row1 = row0 + 8;
#pragma unroll
        for (int nt = 0; nt < 8; nt++) {
            int col = wn * 64 + nt * 8 + kbase;
            if (row0 < NN) {
                __nv_bfloat162 v = __floats2bfloat162_rn(acc[mt][nt][0], acc[mt][nt][1]);
                *(__nv_bfloat162*)&Y[(size_t)row0 * HIDD + col] = v;
            }
            if (row1 < NN) {
                __nv_bfloat162 v = __floats2bfloat162_rn(acc[mt][nt][2], acc[mt][nt][3]);
                *(__nv_bfloat162*)&Y[(size_t)row1 * HIDD + col] = v;
            }
        }
    }
}

// ---------------- aggregation (bf16 gather -> bf16 out) -------------------------
// a16[n] = relu(dinv[n]*(sum_e w_e*h[src] + dinv[n]*h[n]) + b)
__global__ void k_aggregate(const unsigned short* __restrict__ Hin,
                            const float* __restrict__ bias) {
    int warp = (blockIdx.x * blockDim.x + threadIdx.x) >> 5;
    int lane = threadIdx.x & 31;
    if (warp >= NN) return;
    int n = warp;
    int c = lane * 4;
    float dn = d_dinv[n];

    ushort4 hv = *(const ushort4*)&Hin[(size_t)n * HIDD + c];
    float4 acc = make_float4(dn * b2f(hv.x), dn * b2f(hv.y),
                             dn * b2f(hv.z), dn * b2f(hv.w));

    int beg = d_rowptr[n], end = d_rowptr[n + 1];
    int e = beg;
    for (; e + 4 <= end; e += 4) {
        uint2 m0 = d_csr[e],     m1 = d_csr[e + 1];
        uint2 m2 = d_csr[e + 2], m3 = d_csr[e + 3];
        float w0 = __uint_as_float(m0.y), w1 = __uint_as_float(m1.y);
        float w2 = __uint_as_float(m2.y), w3 = __uint_as_float(m3.y);
        ushort4 h0 = *(const ushort4*)&Hin[(size_t)m0.x * HIDD + c];
        ushort4 h1 = *(const ushort4*)&Hin[(size_t)m1.x * HIDD + c];
        ushort4 h2 = *(const ushort4*)&Hin[(size_t)m2.x * HIDD + c];
        ushort4 h3 = *(const ushort4*)&Hin[(size_t)m3.x * HIDD + c];
        acc.x += w0 * b2f(h0.x) + w1 * b2f(h1.x) + w2 * b2f(h2.x) + w3 * b2f(h3.x);
        acc.y += w0 * b2f(h0.y) + w1 * b2f(h1.y) + w2 * b2f(h2.y) + w3 * b2f(h3.y);
        acc.z += w0 * b2f(h0.z) + w1 * b2f(h1.z) + w2 * b2f(h2.z) + w3 * b2f(h3.z);
        acc.w += w0 * b2f(h0.w) + w1 * b2f(h1.w) + w2 * b2f(h2.w) + w3 * b2f(h3.w);
    }
    for (; e < end; e++) {
        uint2 m = d_csr[e];
        float w = __uint_as_float(m.y);
        ushort4 hs = *(const ushort4*)&Hin[(size_t)m.x * HIDD + c];
        acc.x += w * b2f(hs.x); acc.y += w * b2f(hs.y);
        acc.z += w * b2f(hs.z); acc.w += w * b2f(hs.w);
    }

    float4 bv = *(const float4*)&bias[c];
    ushort4 hs4;
    hs4.x = f2b(fmaxf(dn * acc.x + bv.x, 0.0f));
    hs4.y = f2b(fmaxf(dn * acc.y + bv.y, 0.0f));
    hs4.z = f2b(fmaxf(dn * acc.z + bv.z, 0.0f));
    hs4.w = f2b(fmaxf(dn * acc.w + bv.w, 0.0f));
    *(ushort4*)&d_a16[(size_t)n * HIDD + c] = hs4;
}

// ---------------- mean pool + FC (bf16 input) -----------------------------------
__global__ void k_pool_fc(const unsigned short* __restrict__ H,
                          const float* __restrict__ Wfc,
                          const float* __restrict__ bfc, float* __restrict__ out) {
    int g = blockIdx.x;
    int j = threadIdx.x;
    int beg = d_gstart[g], end = d_gstart[g + 1];
    float s = 0.0f;
    for (int r = beg; r < end; r++) s += b2f(H[(size_t)r * HIDD + j]);
    float cntf = fmaxf((float)(end - beg), 1.0f);
    __shared__ float smem[HIDD];
    smem[j] = s / cntf;
    __syncthreads();
    if (j < NCLS) {
        float a = bfc[j];
        for (int k = 0; k < HIDD; k++) a += smem[k] * Wfc[k * NCLS + j];
        out[g * NCLS + j] = a;
    }
}

// ---------------- launch ------------------------------------------------------
extern "C" void kernel_launch(void* const* d_in, const int* in_sizes, int n_in,
                              void* d_out, int out_size) {
    const float* x     = (const float*)d_in[0];
    const void*  ei    = d_in[1];
    const void*  batch = d_in[2];
    const float* W1 = (const float*)d_in[3];  const float* b1 = (const float*)d_in[4];
    const float* W2 = (const float*)d_in[5];  const float* b2 = (const float*)d_in[6];
    const float* W3 = (const float*)d_in[7];  const float* b3 = (const float*)d_in[8];
    const float* W4 = (const float*)d_in[9];  const float* b4 = (const float*)d_in[10];
    const float* Wfc = (const float*)d_in[11]; const float* bfc = (const float*)d_in[12];
    float* out = (float*)d_out;

    cudaFuncSetAttribute(k_hgemm, cudaFuncAttributeMaxDynamicSharedMemorySize, HG_SMEM);

    void* p;
    cudaGetSymbolAddress(&p, d_hb16);   unsigned short* hb16 = (unsigned short*)p;
    cudaGetSymbolAddress(&p, d_a16);    unsigned short* a16 = (unsigned short*)p;
    cudaGetSymbolAddress(&p, d_cnt);    int* cnt = (int*)p;
    cudaGetSymbolAddress(&p, d_incl);   int* incl = (int*)p;
    cudaGetSymbolAddress(&p, d_bsums);  int* bsums = (int*)p;
    cudaGetSymbolAddress(&p, d_rowptr); int* rowptr = (int*)p;
    cudaGetSymbolAddress(&p, d_wp);     uint4* wp = (uint4*)p;

    const int TPB = 256;
    int gN  = (NN + TPB - 1) / TPB;
    int gE  = (NE + TPB - 1) / TPB;
    int gW  = (NN * 32 + TPB - 1) / TPB;
    int nbN = (NN + 1023) / 1024;
    int gGC = 3 + (NG + 1 + TPB - 1) / TPB;   // convW blocks + gstart blocks
    int nT  = (NN + 127) / 128;

    // preprocessing (fused where possible)
    k_zero_detect<<<gN, TPB>>>((const int*)ei, (const int*)batch);
    k_count_deg<<<gE, TPB>>>(ei);
    k_scan_block<<<nbN, 1024>>>(cnt, incl, bsums, NN);
    k_scan_bsums<<<1, 32>>>(bsums, nbN);
    k_scan_final<<<nbN, 1024>>>(cnt, incl, bsums, rowptr, NN);
    k_fill_csr<<<gE, TPB>>>(ei);
    k_gstart_convW<<<gGC, TPB>>>(batch, W2, W3, W4);

    // layer 1 (fused aggregate + transform)
    k_layer1<<<gW, TPB>>>(x, W1, b1);

    // layers 2-4
    k_hgemm<<<nT, 256, HG_SMEM>>>(a16, wp, hb16);
    k_aggregate<<<gW, TPB>>>(hb16, b2);
    k_hgemm<<<nT, 256, HG_SMEM>>>(a16, wp + 4096, hb16);
    k_aggregate<<<gW, TPB>>>(hb16, b3);
    k_hgemm<<<nT, 256, HG_SMEM>>>(a16, wp + 2 * 4096, hb16);
    k_aggregate<<<gW, TPB>>>(hb16, b4);

    // pool + fc (reads bf16 a16)
    k_pool_fc<<<NG, HIDD>>>(a16, Wfc, bfc, out);
}

// round 16
// speedup vs baseline: 1.2606x; 1.0416x over previous
#include <cuda_runtime.h>
#include <cuda_bf16.h>
#include <cstdint>

#define NN   100000
#define NE   640000
#define NG   2048
#define HIDD 128
#define NCLS 4

// ---------------- scratch (static device globals; no allocation) -------------
__device__ unsigned short d_hb16[(size_t)NN * HIDD]; // bf16 gemm output (gather src)
__device__ unsigned short d_a16[(size_t)NN * HIDD];  // bf16 aggregate output (gemm A / pool src)
__device__ uint4  d_wp[3 * 4096];   // fragment-packed W {hi.x,hi.y,lo.x,lo.y}
__device__ float  d_dinv[NN];
__device__ int    d_cnt[NN];
__device__ int    d_incl[NN];
__device__ int    d_bsums[256];
__device__ int    d_rowptr[NN + 1];
__device__ int    d_fill[NN];
__device__ uint2  d_csr[NE];        // packed {src, bits(w)}
__device__ int    d_gstart[NG + 1];
__device__ int    d_ei64;
__device__ int    d_b64;

// ---------------- helpers ------------------------------------------------------
__device__ __forceinline__ int idx_at(const void* p, long long i, int is64) {
    if (is64) return (int)((const long long*)p)[i];
    return ((const int*)p)[i];
}
__device__ __forceinline__ void split1(float v, unsigned short& hi, unsigned short& lo) {
    __nv_bfloat16 h = __float2bfloat16(v);
    float hf = __bfloat162float(h);
    __nv_bfloat16 l = __float2bfloat16(v - hf);
    hi = *(unsigned short*)&h;
    lo = *(unsigned short*)&l;
}
__device__ __forceinline__ unsigned short f2b(float v) {
    __nv_bfloat16 h = __float2bfloat16(v);
    return *(unsigned short*)&h;
}
__device__ __forceinline__ float b2f(unsigned short u) {
    return __uint_as_float((uint32_t)u << 16);
}
__device__ __forceinline__ uint32_t cvta_s(const void* p) {
    uint32_t a;
    asm("{ .reg .u64 t; cvta.to.shared.u64 t, %1; cvt.u32.u64 %0, t; }" : "=r"(a) : "l"(p));
    return a;
}
#define CP16(dst, src)      asm volatile("cp.async.cg.shared.global [%0], [%1], 16;" :: "r"(dst), "l"(src))
#define CP16Z(dst, src, sz) asm volatile("cp.async.cg.shared.global [%0], [%1], 16, %2;" :: "r"(dst), "l"(src), "r"(sz))
#define CPCOMMIT()          asm volatile("cp.async.commit_group;" ::: "memory")
#define CPWAIT()            asm volatile("cp.async.wait_group 0;" ::: "memory")

__device__ __forceinline__ void mma16816(float* c, const uint32_t* a, uint32_t b0, uint32_t b1) {
    asm volatile(
        "mma.sync.aligned.m16n8k16.row.col.f32.bf16.bf16.f32 "
        "{%0,%1,%2,%3}, {%4,%5,%6,%7}, {%8,%9}, {%0,%1,%2,%3};"
        : "+f"(c[0]), "+f"(c[1]), "+f"(c[2]), "+f"(c[3])
        : "r"(a[0]), "r"(a[1]), "r"(a[2]), "r"(a[3]), "r"(b0), "r"(b1));
}

// ---------------- preprocessing ----------------------------------------------
// fused: zero counts + dtype detection (block 0)
__global__ void k_zero_detect(const int* __restrict__ ei32, const int* __restrict__ b32) {
    int i = blockIdx.x * blockDim.x + threadIdx.x;
    if (i < NN) { d_cnt[i] = 0; d_fill[i] = 0; }
    if (blockIdx.x == 0) {
        __shared__ int ef, bf;
        int t = threadIdx.x;
        if (t == 0) { ef = 0; bf = 0; }
        __syncthreads();
        if (t < 128) {
            if (ei32[2 * t + 1] != 0) atomicOr(&ef, 1);
            int base = (NN / 4) & ~1;
            if (b32[base + 2 * t + 1] != 0) atomicOr(&bf, 1);
        }
        __syncthreads();
        if (t == 0) { d_ei64 = ef ? 0 : 1; d_b64 = bf ? 0 : 1; }
    }
}

__global__ void k_count_deg(const void* __restrict__ ei) {
    int e = blockIdx.x * blockDim.x + threadIdx.x;
    int is64 = d_ei64;
    if (e < NE) atomicAdd(&d_cnt[idx_at(ei, (long long)NE + e, is64)], 1);
}

// warp-shuffle inclusive scan over 1024-thread blocks; also emits dinv
__global__ void k_scan_block(const int* __restrict__ in, int* __restrict__ incl,
                             int* __restrict__ bsums, int n) {
    __shared__ int wsum[32];
    int tid = threadIdx.x;
    int lane = tid & 31, wid = tid >> 5;
    int i = blockIdx.x * 1024 + tid;
    int v = (i < n) ? in[i] : 0;
    if (i < n) d_dinv[i] = rsqrtf((float)(v + 1));  // +1 self loop

    int s = v;
#pragma unroll
    for (int off = 1; off < 32; off <<= 1) {
        int t = __shfl_up_sync(0xFFFFFFFFu, s, off);
        if (lane >= off) s += t;
    }
    if (lane == 31) wsum[wid] = s;
    __syncthreads();
    if (wid == 0) {
        int w = wsum[lane];
#pragma unroll
        for (int off = 1; off < 32; off <<= 1) {
            int t = __shfl_up_sync(0xFFFFFFFFu, w, off);
            if (lane >= off) w += t;
        }
        wsum[lane] = w;
    }
    __syncthreads();
    int total = s + (wid ? wsum[wid - 1] : 0);
    if (i < n) incl[i] = total;
    if (tid == 1023) bsums[blockIdx.x] = total;
}

// parallel exclusive scan of block sums (nb <= 128), single 128-thread block
__global__ void k_scan_bsums(int* bsums, int nb) {
    __shared__ int ws[4];
    int tid = threadIdx.x;
    int lane = tid & 31, wid = tid >> 5;
    int v = (tid < nb) ? bsums[tid] : 0;
    int s = v;
#pragma unroll
    for (int off = 1; off < 32; off <<= 1) {
        int t = __shfl_up_sync(0xFFFFFFFFu, s, off);
        if (lane >= off) s += t;
    }
    if (lane == 31) ws[wid] = s;
    __syncthreads();
    int woff = 0;
#pragma unroll
    for (int w = 0; w < 4; w++) if (w < wid) woff += ws[w];
    if (tid < nb) bsums[tid] = s + woff - v;   // exclusive prefix
}

__global__ void k_scan_final(const int* __restrict__ in, const int* __restrict__ incl,
                             const int* __restrict__ bsums, int* __restrict__ out, int n) {
    int i = blockIdx.x * 1024 + threadIdx.x;
    if (i < n) {
        int off = bsums[i >> 10];
        out[i] = incl[i] - in[i] + off;
        if (i == n - 1) out[n] = incl[i] + off;
    }
}

__global__ void k_fill_csr(const void* __restrict__ ei) {
    int e = blockIdx.x * blockDim.x + threadIdx.x;
    int is64 = d_ei64;
    if (e < NE) {
        int r = idx_at(ei, e, is64);
        int c = idx_at(ei, (long long)NE + e, is64);
        int pos = d_rowptr[c] + atomicAdd(&d_fill[c], 1);
        float w = d_dinv[r];
        d_csr[pos] = make_uint2((uint32_t)r, __float_as_uint(w));
    }
}

// fused: blocks 0..2 -> convW (W2..W4 fragment-pack); blocks 3.. -> gstart
__global__ void k_gstart_convW(const void* __restrict__ batch,
                               const float* __restrict__ Wa, const float* __restrict__ Wb,
                               const float* __restrict__ Wc) {
    if (blockIdx.x < 3) {
        int layer = blockIdx.x;
        const float* W = (layer == 0) ? Wa : (layer == 1) ? Wb : Wc;
        uint4* pw = d_wp + layer * 4096;
        for (int idx = threadIdx.x; idx < 4096; idx += blockDim.x) {
            int lane = idx & 31;
            int nt = (idx >> 5) & 15;
            int kk = idx >> 9;
            int n = nt * 8 + (lane >> 2);
            int k0 = kk * 16 + (lane & 3) * 2;
            unsigned short h0, h1, h2, h3, l0, l1, l2, l3;
            split1(W[k0 * HIDD + n], h0, l0);
            split1(W[(k0 + 1) * HIDD + n], h1, l1);
            split1(W[(k0 + 8) * HIDD + n], h2, l2);
            split1(W[(k0 + 9) * HIDD + n], h3, l3);
            pw[idx] = make_uint4((uint32_t)h0 | ((uint32_t)h1 << 16),
                                 (uint32_t)h2 | ((uint32_t)h3 << 16),
                                 (uint32_t)l0 | ((uint32_t)l1 << 16),
                                 (uint32_t)l2 | ((uint32_t)l3 << 16));
        }
    } else {
        int g = (blockIdx.x - 3) * blockDim.x + threadIdx.x;
        if (g > NG) return;
        int is64 = d_b64;
        int lo = 0, hi = NN;
        while (lo < hi) {
            int mid = (lo + hi) >> 1;
            if (idx_at(batch, mid, is64) < g) lo = mid + 1; else hi = mid;
        }
        d_gstart[g] = lo;
    }
}

// ---------------- layer 1 fused: aggregate x (3ch) + transform + relu -> a16 ---
__global__ void k_layer1(const float* __restrict__ X, const float* __restrict__ W1,
                         const float* __restrict__ b1) {
    int n = (blockIdx.x * blockDim.x + threadIdx.x) >> 5;
    int lane = threadIdx.x & 31;
    if (n >= NN) return;
    float dn = d_dinv[n];

    int beg = d_rowptr[n], end = d_rowptr[n + 1];
    float a0 = 0.f, a1 = 0.f, a2 = 0.f;
    for (int e = beg + lane; e < end; e += 32) {
        uint2 m = d_csr[e];
        int s = (int)m.x;
        float w = __uint_as_float(m.y);
        a0 += w * X[s * 3 + 0];
        a1 += w * X[s * 3 + 1];
        a2 += w * X[s * 3 + 2];
    }
#pragma unroll
    for (int off = 16; off > 0; off >>= 1) {
        a0 += __shfl_down_sync(0xFFFFFFFFu, a0, off);
        a1 += __shfl_down_sync(0xFFFFFFFFu, a1, off);
        a2 += __shfl_down_sync(0xFFFFFFFFu, a2, off);
    }
    a0 = __shfl_sync(0xFFFFFFFFu, a0, 0);
    a1 = __shfl_sync(0xFFFFFFFFu, a1, 0);
    a2 = __shfl_sync(0xFFFFFFFFu, a2, 0);

    float x0 = dn * (a0 + dn * X[n * 3 + 0]);
    float x1 = dn * (a1 + dn * X[n * 3 + 1]);
    float x2 = dn * (a2 + dn * X[n * 3 + 2]);

    float4 w0 = *(const float4*)&W1[0 * HIDD + lane * 4];
    float4 w1 = *(const float4*)&W1[1 * HIDD + lane * 4];
    float4 w2 = *(const float4*)&W1[2 * HIDD + lane * 4];
    float4 bv = *(const float4*)&b1[lane * 4];
    ushort4 hv;
    hv.x = f2b(fmaxf(x0 * w0.x + x1 * w1.x + x2 * w2.x + bv.x, 0.0f));
    hv.y = f2b(fmaxf(x0 * w0.y + x1 * w1.y + x2 * w2.y + bv.y, 0.0f));
    hv.z = f2b(fmaxf(x0 * w0.z + x1 * w1.z + x2 * w2.z + bv.z, 0.0f));
    hv.w = f2b(fmaxf(x0 * w0.w + x1 * w1.w + x2 * w2.w + bv.w, 0.0f));
    *(ushort4*)&d_a16[(size_t)n * HIDD + lane * 4] = hv;
}

// ---------------- HMMA GEMM: persistent blocks, W staged once ------------------
// grid = 296 (2 CTA/SM). Each block: stage W once, then loop tiles stride-grid.
#define HGA_STRIDE 136
#define HG_SMEM (65536 + 128 * HGA_STRIDE * 2)   // 100352 B
#define HG_GRID 296

__global__ void __launch_bounds__(256, 2)
k_hgemm(const unsigned short* __restrict__ A16,
        const uint4* __restrict__ WP,
        unsigned short* __restrict__ Y, int nTiles) {
    extern __shared__ char smraw[];
    uint4* sW = (uint4*)smraw;                               // [4096]
    unsigned short* sA = (unsigned short*)(smraw + 65536);   // [128][136]

    int tid = threadIdx.x;
    uint32_t sWa = cvta_s(sW);
    uint32_t sAa = cvta_s(sA);

    // stage W once per block
    for (int i = tid; i < 4096; i += 256)
        CP16(sWa + i * 16, &WP[i]);
    CPCOMMIT();

    int warp = tid >> 5, lane = tid & 31;
    int wm = warp & 3;
    int wn = warp >> 2;
    int tr0 = wm * 32 + (lane >> 2);
    int tr1 = tr0 + 16;
    int kbase = (lane & 3) * 2;

    for (int t = blockIdx.x; t < nTiles; t += HG_GRID) {
        int rb = t * 128;
        // stage A tile
        for (int i = tid; i < 128 * 16; i += 256) {
            int r = i >> 4, seg = i & 15;
            int gr = rb + r;
            const unsigned short* src = &A16[(size_t)min(gr, NN - 1) * HIDD + seg * 8];
            uint32_t sz = (gr < NN) ? 16u : 0u;
            CP16Z(sAa + (r * HGA_STRIDE + seg * 8) * 2, src, sz);
        }
        CPCOMMIT();
        CPWAIT();
        __syncthreads();

        float acc[2][8][4];
#pragma unroll
        for (int mt = 0; mt < 2; mt++)
#pragma unroll
            for (int nt = 0; nt < 8; nt++)
#pragma unroll
                for (int j = 0; j < 4; j++) acc[mt][nt][j] = 0.0f;

#pragma unroll
        for (int kk = 0; kk < 8; kk++) {
            int kc = kk * 16 + kbase;
            uint32_t a0[4], a1[4];
            a0[0] = *(const uint32_t*)&sA[tr0 * HGA_STRIDE + kc];
            a0[1] = *(const uint32_t*)&sA[(tr0 + 8) * HGA_STRIDE + kc];
            a0[2] = *(const uint32_t*)&sA[tr0 * HGA_STRIDE + kc + 8];
            a0[3] = *(const uint32_t*)&sA[(tr0 + 8) * HGA_STRIDE + kc + 8];
            a1[0] = *(const uint32_t*)&sA[tr1 * HGA_STRIDE + kc];
            a1[1] = *(const uint32_t*)&sA[(tr1 + 8) * HGA_STRIDE + kc];
            a1[2] = *(const uint32_t*)&sA[tr1 * HGA_STRIDE + kc + 8];
            a1[3] = *(const uint32_t*)&sA[(tr1 + 8) * HGA_STRIDE + kc + 8];
            const uint4* bp = &sW[kk * 512 + wn * 256 + lane];
#pragma unroll
            for (int nt = 0; nt < 8; nt++) {
                uint4 w = bp[nt * 32];
                mma16816(acc[0][nt], a0, w.x, w.y);
                mma16816(acc[0][nt], a0, w.z, w.w);
                mma16816(acc[1][nt], a1, w.x, w.y);
                mma16816(acc[1][nt], a1, w.z, w.w);
            }
        }

#pragma unroll
        for (int mt = 0; mt < 2; mt++) {
            int row0 = rb + tr0 + mt * 16;
            int row1 = row0 + 8;
#pragma unroll
            for (int nt = 0; nt < 8; nt++) {
                int col = wn * 64 + nt * 8 + kbase;
                if (row0 < NN) {
                    __nv_bfloat162 v = __floats2bfloat162_rn(acc[mt][nt][0], acc[mt][nt][1]);
                    *(__nv_bfloat162*)&Y[(size_t)row0 * HIDD + col] = v;
                }
                if (row1 < NN) {
                    __nv_bfloat162 v = __floats2bfloat162_rn(acc[mt][nt][2], acc[mt][nt][3]);
                    *(__nv_bfloat162*)&Y[(size_t)row1 * HIDD + col] = v;
                }
            }
        }
        __syncthreads();   // all warps done reading sA before next stage
    }
}

// ---------------- aggregation (bf16 gather -> bf16 out) -------------------------
__global__ void k_aggregate(const unsigned short* __restrict__ Hin,
                            const float* __restrict__ bias) {
    int warp = (blockIdx.x * blockDim.x + threadIdx.x) >> 5;
    int lane = threadIdx.x & 31;
    if (warp >= NN) return;
    int n = warp;
    int c = lane * 4;
    float dn = d_dinv[n];

    ushort4 hv = *(const ushort4*)&Hin[(size_t)n * HIDD + c];
    float4 acc = make_float4(dn * b2f(hv.x), dn * b2f(hv.y),
                             dn * b2f(hv.z), dn * b2f(hv.w));

    int beg = d_rowptr[n], end = d_rowptr[n + 1];
    int e = beg;
    for (; e + 4 <= end; e += 4) {
        uint2 m0 = d_csr[e],     m1 = d_csr[e + 1];
        uint2 m2 = d_csr[e + 2], m3 = d_csr[e + 3];
        float w0 = __uint_as_float(m0.y), w1 = __uint_as_float(m1.y);
        float w2 = __uint_as_float(m2.y), w3 = __uint_as_float(m3.y);
        ushort4 h0 = *(const ushort4*)&Hin[(size_t)m0.x * HIDD + c];
        ushort4 h1 = *(const ushort4*)&Hin[(size_t)m1.x * HIDD + c];
        ushort4 h2 = *(const ushort4*)&Hin[(size_t)m2.x * HIDD + c];
        ushort4 h3 = *(const ushort4*)&Hin[(size_t)m3.x * HIDD + c];
        acc.x += w0 * b2f(h0.x) + w1 * b2f(h1.x) + w2 * b2f(h2.x) + w3 * b2f(h3.x);
        acc.y += w0 * b2f(h0.y) + w1 * b2f(h1.y) + w2 * b2f(h2.y) + w3 * b2f(h3.y);
        acc.z += w0 * b2f(h0.z) + w1 * b2f(h1.z) + w2 * b2f(h2.z) + w3 * b2f(h3.z);
        acc.w += w0 * b2f(h0.w) + w1 * b2f(h1.w) + w2 * b2f(h2.w) + w3 * b2f(h3.w);
    }
    for (; e < end; e++) {
        uint2 m = d_csr[e];
        float w = __uint_as_float(m.y);
        ushort4 hs = *(const ushort4*)&Hin[(size_t)m.x * HIDD + c];
        acc.x += w * b2f(hs.x); acc.y += w * b2f(hs.y);
        acc.z += w * b2f(hs.z); acc.w += w * b2f(hs.w);
    }

    float4 bv = *(const float4*)&bias[c];
    ushort4 hs4;
    hs4.x = f2b(fmaxf(dn * acc.x + bv.x, 0.0f));
    hs4.y = f2b(fmaxf(dn * acc.y + bv.y, 0.0f));
    hs4.z = f2b(fmaxf(dn * acc.z + bv.z, 0.0f));
    hs4.w = f2b(fmaxf(dn * acc.w + bv.w, 0.0f));
    *(ushort4*)&d_a16[(size_t)n * HIDD + c] = hs4;
}

// ---------------- mean pool + FC (bf16 input) -----------------------------------
__global__ void k_pool_fc(const unsigned short* __restrict__ H,
                          const float* __restrict__ Wfc,
                          const float* __restrict__ bfc, float* __restrict__ out) {
    int g = blockIdx.x;
    int j = threadIdx.x;
    int beg = d_gstart[g], end = d_gstart[g + 1];
    float s = 0.0f;
    for (int r = beg; r < end; r++) s += b2f(H[(size_t)r * HIDD + j]);
    float cntf = fmaxf((float)(end - beg), 1.0f);
    __shared__ float smem[HIDD];
    smem[j] = s / cntf;
    __syncthreads();
    if (j < NCLS) {
        float a = bfc[j];
        for (int k = 0; k < HIDD; k++) a += smem[k] * Wfc[k * NCLS + j];
        out[g * NCLS + j] = a;
    }
}

// ---------------- launch ------------------------------------------------------
extern "C" void kernel_launch(void* const* d_in, const int* in_sizes, int n_in,
                              void* d_out, int out_size) {
    const float* x     = (const float*)d_in[0];
    const void*  ei    = d_in[1];
    const void*  batch = d_in[2];
    const float* W1 = (const float*)d_in[3];  const float* b1 = (const float*)d_in[4];
    const float* W2 = (const float*)d_in[5];  const float* b2 = (const float*)d_in[6];
    const float* W3 = (const float*)d_in[7];  const float* b3 = (const float*)d_in[8];
    const float* W4 = (const float*)d_in[9];  const float* b4 = (const float*)d_in[10];
    const float* Wfc = (const float*)d_in[11]; const float* bfc = (const float*)d_in[12];
    float* out = (float*)d_out;

    cudaFuncSetAttribute(k_hgemm, cudaFuncAttributeMaxDynamicSharedMemorySize, HG_SMEM);

    void* p;
    cudaGetSymbolAddress(&p, d_hb16);   unsigned short* hb16 = (unsigned short*)p;
    cudaGetSymbolAddress(&p, d_a16);    unsigned short* a16 = (unsigned short*)p;
    cudaGetSymbolAddress(&p, d_cnt);    int* cnt = (int*)p;
    cudaGetSymbolAddress(&p, d_incl);   int* incl = (int*)p;
    cudaGetSymbolAddress(&p, d_bsums);  int* bsums = (int*)p;
    cudaGetSymbolAddress(&p, d_rowptr); int* rowptr = (int*)p;
    cudaGetSymbolAddress(&p, d_wp);     uint4* wp = (uint4*)p;

    const int TPB = 256;
    int gN  = (NN + TPB - 1) / TPB;
    int gE  = (NE + TPB - 1) / TPB;
    int gW  = (NN * 32 + TPB - 1) / TPB;
    int nbN = (NN + 1023) / 1024;
    int gGC = 3 + (NG + 1 + TPB - 1) / TPB;
    int nT  = (NN + 127) / 128;

    // preprocessing
    k_zero_detect<<<gN, TPB>>>((const int*)ei, (const int*)batch);
    k_count_deg<<<gE, TPB>>>(ei);
    k_scan_block<<<nbN, 1024>>>(cnt, incl, bsums, NN);
    k_scan_bsums<<<1, 128>>>(bsums, nbN);
    k_scan_final<<<nbN, 1024>>>(cnt, incl, bsums, rowptr, NN);
    k_fill_csr<<<gE, TPB>>>(ei);
    k_gstart_convW<<<gGC, TPB>>>(batch, W2, W3, W4);

    // layer 1 (fused aggregate + transform)
    k_layer1<<<gW, TPB>>>(x, W1, b1);

    // layers 2-4: persistent HMMA gemm then aggregate
    k_hgemm<<<HG_GRID, 256, HG_SMEM>>>(a16, wp, hb16, nT);
    k_aggregate<<<gW, TPB>>>(hb16, b2);
    k_hgemm<<<HG_GRID, 256, HG_SMEM>>>(a16, wp + 4096, hb16, nT);
    k_aggregate<<<gW, TPB>>>(hb16, b3);
    k_hgemm<<<HG_GRID, 256, HG_SMEM>>>(a16, wp + 2 * 4096, hb16, nT);
    k_aggregate<<<gW, TPB>>>(hb16, b4);

    // pool + fc (reads bf16 a16)
    k_pool_fc<<<NG, HIDD>>>(a16, Wfc, bfc, out);
}

// round 17
// speedup vs baseline: 1.2865x; 1.0205x over previous
#include <cuda_runtime.h>
#include <cuda_bf16.h>
#include <cstdint>

#define NN   100000
#define NE   640000
#define NG   2048
#define HIDD 128
#define NCLS 4

// ---------------- scratch (static device globals; no allocation) -------------
__device__ unsigned short d_hb16[(size_t)NN * HIDD]; // bf16 gemm output (gather src)
__device__ unsigned short d_a16[(size_t)NN * HIDD];  // bf16 aggregate output (gemm A / pool src)
__device__ uint4  d_wp[3 * 4096];   // fragment-packed W {hi.x,hi.y,lo.x,lo.y}
__device__ float  d_dinv[NN];
__device__ int    d_cnt[NN];
__device__ int    d_incl[NN];
__device__ int    d_bsums[256];
__device__ int    d_rowptr[NN + 1];
__device__ int    d_fill[NN];
__device__ uint2  d_csr[NE];        // packed {src, bits(w)}
__device__ int    d_gstart[NG + 1];
__device__ int    d_ei64;
__device__ int    d_b64;

// ---------------- helpers ------------------------------------------------------
__device__ __forceinline__ int idx_at(const void* p, long long i, int is64) {
    if (is64) return (int)((const long long*)p)[i];
    return ((const int*)p)[i];
}
__device__ __forceinline__ void split1(float v, unsigned short& hi, unsigned short& lo) {
    __nv_bfloat16 h = __float2bfloat16(v);
    float hf = __bfloat162float(h);
    __nv_bfloat16 l = __float2bfloat16(v - hf);
    hi = *(unsigned short*)&h;
    lo = *(unsigned short*)&l;
}
__device__ __forceinline__ unsigned short f2b(float v) {
    __nv_bfloat16 h = __float2bfloat16(v);
    return *(unsigned short*)&h;
}
__device__ __forceinline__ float b2f(unsigned short u) {
    return __uint_as_float((uint32_t)u << 16);
}
__device__ __forceinline__ uint32_t cvta_s(const void* p) {
    uint32_t a;
    asm("{ .reg .u64 t; cvta.to.shared.u64 t, %1; cvt.u32.u64 %0, t; }" : "=r"(a) : "l"(p));
    return a;
}
#define CP16(dst, src)      asm volatile("cp.async.cg.shared.global [%0], [%1], 16;" :: "r"(dst), "l"(src))
#define CP16Z(dst, src, sz) asm volatile("cp.async.cg.shared.global [%0], [%1], 16, %2;" :: "r"(dst), "l"(src), "r"(sz))
#define CPCOMMIT()          asm volatile("cp.async.commit_group;" ::: "memory")
#define CPWAIT()            asm volatile("cp.async.wait_group 0;" ::: "memory")

__device__ __forceinline__ void mma16816(float* c, const uint32_t* a, uint32_t b0, uint32_t b1) {
    asm volatile(
        "mma.sync.aligned.m16n8k16.row.col.f32.bf16.bf16.f32 "
        "{%0,%1,%2,%3}, {%4,%5,%6,%7}, {%8,%9}, {%0,%1,%2,%3};"
        : "+f"(c[0]), "+f"(c[1]), "+f"(c[2]), "+f"(c[3])
        : "r"(a[0]), "r"(a[1]), "r"(a[2]), "r"(a[3]), "r"(b0), "r"(b1));
}

// ---------------- preprocessing ----------------------------------------------
// fused: zero counts + dtype detection (block 0)
__global__ void k_zero_detect(const int* __restrict__ ei32, const int* __restrict__ b32) {
    int i = blockIdx.x * blockDim.x + threadIdx.x;
    if (i < NN) { d_cnt[i] = 0; d_fill[i] = 0; }
    if (blockIdx.x == 0) {
        __shared__ int ef, bf;
        int t = threadIdx.x;
        if (t == 0) { ef = 0; bf = 0; }
        __syncthreads();
        if (t < 128) {
            if (ei32[2 * t + 1] != 0) atomicOr(&ef, 1);
            int base = (NN / 4) & ~1;
            if (b32[base + 2 * t + 1] != 0) atomicOr(&bf, 1);
        }
        __syncthreads();
        if (t == 0) { d_ei64 = ef ? 0 : 1; d_b64 = bf ? 0 : 1; }
    }
}

__global__ void k_count_deg(const void* __restrict__ ei) {
    int e = blockIdx.x * blockDim.x + threadIdx.x;
    int is64 = d_ei64;
    if (e < NE) atomicAdd(&d_cnt[idx_at(ei, (long long)NE + e, is64)], 1);
}

// warp-shuffle inclusive scan over 1024-thread blocks; also emits dinv.
// bsums[b] holds RAW per-block totals (not scanned).
__global__ void k_scan_block(const int* __restrict__ in, int* __restrict__ incl,
                             int* __restrict__ bsums, int n) {
    __shared__ int wsum[32];
    int tid = threadIdx.x;
    int lane = tid & 31, wid = tid >> 5;
    int i = blockIdx.x * 1024 + tid;
    int v = (i < n) ? in[i] : 0;
    if (i < n) d_dinv[i] = rsqrtf((float)(v + 1));  // +1 self loop

    int s = v;
#pragma unroll
    for (int off = 1; off < 32; off <<= 1) {
        int t = __shfl_up_sync(0xFFFFFFFFu, s, off);
        if (lane >= off) s += t;
    }
    if (lane == 31) wsum[wid] = s;
    __syncthreads();
    if (wid == 0) {
        int w = wsum[lane];
#pragma unroll
        for (int off = 1; off < 32; off <<= 1) {
            int t = __shfl_up_sync(0xFFFFFFFFu, w, off);
            if (lane >= off) w += t;
        }
        wsum[lane] = w;
    }
    __syncthreads();
    int total = s + (wid ? wsum[wid - 1] : 0);
    if (i < n) incl[i] = total;
    if (tid == 1023) bsums[blockIdx.x] = total;
}

// final scan stage: each block reduces raw bsums[0..bid) itself (nb <= 128)
__global__ void k_scan_final(const int* __restrict__ in, const int* __restrict__ incl,
                             const int* __restrict__ bsums, int* __restrict__ out,
                             int n, int nb) {
    __shared__ int red[128];
    __shared__ int soff;
    int tid = threadIdx.x;
    int bid = blockIdx.x;
    if (tid < 128) red[tid] = (tid < bid && tid < nb) ? bsums[tid] : 0;
    __syncthreads();
    if (tid < 64) red[tid] += red[tid + 64];
    __syncthreads();
    if (tid < 32) {
        int v = red[tid] + red[tid + 32];
#pragma unroll
        for (int off = 16; off > 0; off >>= 1)
            v += __shfl_down_sync(0xFFFFFFFFu, v, off);
        if (tid == 0) soff = v;
    }
    __syncthreads();
    int off = soff;
    int i = bid * 1024 + tid;
    if (i < n) {
        out[i] = incl[i] - in[i] + off;          // exclusive prefix
        if (i == n - 1) out[n] = incl[i] + off;  // total
    }
}

// fused: blocks [0, gE) fill CSR; blocks [gE, gE+3) convW; rest gstart
__global__ void k_fill_gstart_convW(const void* __restrict__ ei,
                                    const void* __restrict__ batch,
                                    const float* __restrict__ Wa,
                                    const float* __restrict__ Wb,
                                    const float* __restrict__ Wc, int gE) {
    if (blockIdx.x < gE) {
        int e = blockIdx.x * blockDim.x + threadIdx.x;
        int is64 = d_ei64;
        if (e < NE) {
            int r = idx_at(ei, e, is64);
            int c = idx_at(ei, (long long)NE + e, is64);
            int pos = d_rowptr[c] + atomicAdd(&d_fill[c], 1);
            float w = d_dinv[r];
            d_csr[pos] = make_uint2((uint32_t)r, __float_as_uint(w));
        }
    } else if (blockIdx.x < gE + 3) {
        int layer = blockIdx.x - gE;
        const float* W = (layer == 0) ? Wa : (layer == 1) ? Wb : Wc;
        uint4* pw = d_wp + layer * 4096;
        for (int idx = threadIdx.x; idx < 4096; idx += blockDim.x) {
            int lane = idx & 31;
            int nt = (idx >> 5) & 15;
            int kk = idx >> 9;
            int n = nt * 8 + (lane >> 2);
            int k0 = kk * 16 + (lane & 3) * 2;
            unsigned short h0, h1, h2, h3, l0, l1, l2, l3;
            split1(W[k0 * HIDD + n], h0, l0);
            split1(W[(k0 + 1) * HIDD + n], h1, l1);
            split1(W[(k0 + 8) * HIDD + n], h2, l2);
            split1(W[(k0 + 9) * HIDD + n], h3, l3);
            pw[idx] = make_uint4((uint32_t)h0 | ((uint32_t)h1 << 16),
                                 (uint32_t)h2 | ((uint32_t)h3 << 16),
                                 (uint32_t)l0 | ((uint32_t)l1 << 16),
                                 (uint32_t)l2 | ((uint32_t)l3 << 16));
        }
    } else {
        int g = (blockIdx.x - gE - 3) * blockDim.x + threadIdx.x;
        if (g > NG) return;
        int is64 = d_b64;
        int lo = 0, hi = NN;
        while (lo < hi) {
            int mid = (lo + hi) >> 1;
            if (idx_at(batch, mid, is64) < g) lo = mid + 1; else hi = mid;
        }
        d_gstart[g] = lo;
    }
}

// ---------------- layer 1 fused: aggregate x (3ch) + transform + relu -> a16 ---
__global__ void k_layer1(const float* __restrict__ X, const float* __restrict__ W1,
                         const float* __restrict__ b1) {
    int n = (blockIdx.x * blockDim.x + threadIdx.x) >> 5;
    int lane = threadIdx.x & 31;
    if (n >= NN) return;
    float dn = d_dinv[n];

    int beg = d_rowptr[n], end = d_rowptr[n + 1];
    float a0 = 0.f, a1 = 0.f, a2 = 0.f;
    for (int e = beg + lane; e < end; e += 32) {
        uint2 m = d_csr[e];
        int s = (int)m.x;
        float w = __uint_as_float(m.y);
        a0 += w * X[s * 3 + 0];
        a1 += w * X[s * 3 + 1];
        a2 += w * X[s * 3 + 2];
    }
#pragma unroll
    for (int off = 16; off > 0; off >>= 1) {
        a0 += __shfl_down_sync(0xFFFFFFFFu, a0, off);
        a1 += __shfl_down_sync(0xFFFFFFFFu, a1, off);
        a2 += __shfl_down_sync(0xFFFFFFFFu, a2, off);
    }
    a0 = __shfl_sync(0xFFFFFFFFu, a0, 0);
    a1 = __shfl_sync(0xFFFFFFFFu, a1, 0);
    a2 = __shfl_sync(0xFFFFFFFFu, a2, 0);

    float x0 = dn * (a0 + dn * X[n * 3 + 0]);
    float x1 = dn * (a1 + dn * X[n * 3 + 1]);
    float x2 = dn * (a2 + dn * X[n * 3 + 2]);

    float4 w0 = *(const float4*)&W1[0 * HIDD + lane * 4];
    float4 w1 = *(const float4*)&W1[1 * HIDD + lane * 4];
    float4 w2 = *(const float4*)&W1[2 * HIDD + lane * 4];
    float4 bv = *(const float4*)&b1[lane * 4];
    ushort4 hv;
    hv.x = f2b(fmaxf(x0 * w0.x + x1 * w1.x + x2 * w2.x + bv.x, 0.0f));
    hv.y = f2b(fmaxf(x0 * w0.y + x1 * w1.y + x2 * w2.y + bv.y, 0.0f));
    hv.z = f2b(fmaxf(x0 * w0.z + x1 * w1.z + x2 * w2.z + bv.z, 0.0f));
    hv.w = f2b(fmaxf(x0 * w0.w + x1 * w1.w + x2 * w2.w + bv.w, 0.0f));
    *(ushort4*)&d_a16[(size_t)n * HIDD + lane * 4] = hv;
}

// ---------------- HMMA GEMM: persistent blocks, W staged once ------------------
#define HGA_STRIDE 136
#define HG_SMEM (65536 + 128 * HGA_STRIDE * 2)   // 100352 B
#define HG_GRID 296

__global__ void __launch_bounds__(256, 2)
k_hgemm(const unsigned short* __restrict__ A16,
        const uint4* __restrict__ WP,
        unsigned short* __restrict__ Y, int nTiles) {
    extern __shared__ char smraw[];
    uint4* sW = (uint4*)smraw;                               // [4096]
    unsigned short* sA = (unsigned short*)(smraw + 65536);   // [128][136]

    int tid = threadIdx.x;
    uint32_t sWa = cvta_s(sW);
    uint32_t sAa = cvta_s(sA);

    // stage W once per block
    for (int i = tid; i < 4096; i += 256)
        CP16(sWa + i * 16, &WP[i]);
    CPCOMMIT();

    int warp = tid >> 5, lane = tid & 31;
    int wm = warp & 3;
    int wn = warp >> 2;
    int tr0 = wm * 32 + (lane >> 2);
    int tr1 = tr0 + 16;
    int kbase = (lane & 3) * 2;

    for (int t = blockIdx.x; t < nTiles; t += HG_GRID) {
        int rb = t * 128;
        // stage A tile
        for (int i = tid; i < 128 * 16; i += 256) {
            int r = i >> 4, seg = i & 15;
            int gr = rb + r;
            const unsigned short* src = &A16[(size_t)min(gr, NN - 1) * HIDD + seg * 8];
            uint32_t sz = (gr < NN) ? 16u : 0u;
            CP16Z(sAa + (r * HGA_STRIDE + seg * 8) * 2, src, sz);
        }
        CPCOMMIT();
        CPWAIT();
        __syncthreads();

        float acc[2][8][4];
#pragma unroll
        for (int mt = 0; mt < 2; mt++)
#pragma unroll
            for (int nt = 0; nt < 8; nt++)
#pragma unroll
                for (int j = 0; j < 4; j++) acc[mt][nt][j] = 0.0f;

#pragma unroll
        for (int kk = 0; kk < 8; kk++) {
            int kc = kk * 16 + kbase;
            uint32_t a0[4], a1[4];
            a0[0] = *(const uint32_t*)&sA[tr0 * HGA_STRIDE + kc];
            a0[1] = *(const uint32_t*)&sA[(tr0 + 8) * HGA_STRIDE + kc];
            a0[2] = *(const uint32_t*)&sA[tr0 * HGA_STRIDE + kc + 8];
            a0[3] = *(const uint32_t*)&sA[(tr0 + 8) * HGA_STRIDE + kc + 8];
            a1[0] = *(const uint32_t*)&sA[tr1 * HGA_STRIDE + kc];
            a1[1] = *(const uint32_t*)&sA[(tr1 + 8) * HGA_STRIDE + kc];
            a1[2] = *(const uint32_t*)&sA[tr1 * HGA_STRIDE + kc + 8];
            a1[3] = *(const uint32_t*)&sA[(tr1 + 8) * HGA_STRIDE + kc + 8];
            const uint4* bp = &sW[kk * 512 + wn * 256 + lane];
#pragma unroll
            for (int nt = 0; nt < 8; nt++) {
                uint4 w = bp[nt * 32];
                mma16816(acc[0][nt], a0, w.x, w.y);
                mma16816(acc[0][nt], a0, w.z, w.w);
                mma16816(acc[1][nt], a1, w.x, w.y);
                mma16816(acc[1][nt], a1, w.z, w.w);
            }
        }

#pragma unroll
        for (int mt = 0; mt < 2; mt++) {
            int row0 = rb + tr0 + mt * 16;
            int row1 = row0 + 8;
#pragma unroll
            for (int nt = 0; nt < 8; nt++) {
                int col = wn * 64 + nt * 8 + kbase;
                if (row0 < NN) {
                    __nv_bfloat162 v = __floats2bfloat162_rn(acc[mt][nt][0], acc[mt][nt][1]);
                    *(__nv_bfloat162*)&Y[(size_t)row0 * HIDD + col] = v;
                }
                if (row1 < NN) {
                    __nv_bfloat162 v = __floats2bfloat162_rn(acc[mt][nt][2], acc[mt][nt][3]);
                    *(__nv_bfloat162*)&Y[(size_t)row1 * HIDD + col] = v;
                }
            }
        }
        __syncthreads();   // all warps done reading sA before next stage
    }
}

// ---------------- aggregation (bf16 gather -> bf16 out) -------------------------
__global__ void k_aggregate(const unsigned short* __restrict__ Hin,
                            const float* __restrict__ bias) {
    int warp = (blockIdx.x * blockDim.x + threadIdx.x) >> 5;
    int lane = threadIdx.x & 31;
    if (warp >= NN) return;
    int n = warp;
    int c = lane * 4;
    float dn = d_dinv[n];

    ushort4 hv = *(const ushort4*)&Hin[(size_t)n * HIDD + c];
    float4 acc = make_float4(dn * b2f(hv.x), dn * b2f(hv.y),
                             dn * b2f(hv.z), dn * b2f(hv.w));

    int beg = d_rowptr[n], end = d_rowptr[n + 1];
    int e = beg;
    for (; e + 4 <= end; e += 4) {
        uint2 m0 = d_csr[e],     m1 = d_csr[e + 1];
        uint2 m2 = d_csr[e + 2], m3 = d_csr[e + 3];
        float w0 = __uint_as_float(m0.y), w1 = __uint_as_float(m1.y);
        float w2 = __uint_as_float(m2.y), w3 = __uint_as_float(m3.y);
        ushort4 h0 = *(const ushort4*)&Hin[(size_t)m0.x * HIDD + c];
        ushort4 h1 = *(const ushort4*)&Hin[(size_t)m1.x * HIDD + c];
        ushort4 h2 = *(const ushort4*)&Hin[(size_t)m2.x * HIDD + c];
        ushort4 h3 = *(const ushort4*)&Hin[(size_t)m3.x * HIDD + c];
        acc.x += w0 * b2f(h0.x) + w1 * b2f(h1.x) + w2 * b2f(h2.x) + w3 * b2f(h3.x);
        acc.y += w0 * b2f(h0.y) + w1 * b2f(h1.y) + w2 * b2f(h2.y) + w3 * b2f(h3.y);
        acc.z += w0 * b2f(h0.z) + w1 * b2f(h1.z) + w2 * b2f(h2.z) + w3 * b2f(h3.z);
        acc.w += w0 * b2f(h0.w) + w1 * b2f(h1.w) + w2 * b2f(h2.w) + w3 * b2f(h3.w);
    }
    for (; e < end; e++) {
        uint2 m = d_csr[e];
        float w = __uint_as_float(m.y);
        ushort4 hs = *(const ushort4*)&Hin[(size_t)m.x * HIDD + c];
        acc.x += w * b2f(hs.x); acc.y += w * b2f(hs.y);
        acc.z += w * b2f(hs.z); acc.w += w * b2f(hs.w);
    }

    float4 bv = *(const float4*)&bias[c];
    ushort4 hs4;
    hs4.x = f2b(fmaxf(dn * acc.x + bv.x, 0.0f));
    hs4.y = f2b(fmaxf(dn * acc.y + bv.y, 0.0f));
    hs4.z = f2b(fmaxf(dn * acc.z + bv.z, 0.0f));
    hs4.w = f2b(fmaxf(dn * acc.w + bv.w, 0.0f));
    *(ushort4*)&d_a16[(size_t)n * HIDD + c] = hs4;
}

// ---------------- mean pool + FC (bf16 input) -----------------------------------
__global__ void k_pool_fc(const unsigned short* __restrict__ H,
                          const float* __restrict__ Wfc,
                          const float* __restrict__ bfc, float* __restrict__ out) {
    int g = blockIdx.x;
    int j = threadIdx.x;
    int beg = d_gstart[g], end = d_gstart[g + 1];
    float s = 0.0f;
    for (int r = beg; r < end; r++) s += b2f(H[(size_t)r * HIDD + j]);
    float cntf = fmaxf((float)(end - beg), 1.0f);
    __shared__ float smem[HIDD];
    smem[j] = s / cntf;
    __syncthreads();
    if (j < NCLS) {
        float a = bfc[j];
        for (int k = 0; k < HIDD; k++) a += smem[k] * Wfc[k * NCLS + j];
        out[g * NCLS + j] = a;
    }
}

// ---------------- launch ------------------------------------------------------
extern "C" void kernel_launch(void* const* d_in, const int* in_sizes, int n_in,
                              void* d_out, int out_size) {
    const float* x     = (const float*)d_in[0];
    const void*  ei    = d_in[1];
    const void*  batch = d_in[2];
    const float* W1 = (const float*)d_in[3];  const float* b1 = (const float*)d_in[4];
    const float* W2 = (const float*)d_in[5];  const float* b2 = (const float*)d_in[6];
    const float* W3 = (const float*)d_in[7];  const float* b3 = (const float*)d_in[8];
    const float* W4 = (const float*)d_in[9];  const float* b4 = (const float*)d_in[10];
    const float* Wfc = (const float*)d_in[11]; const float* bfc = (const float*)d_in[12];
    float* out = (float*)d_out;

    cudaFuncSetAttribute(k_hgemm, cudaFuncAttributeMaxDynamicSharedMemorySize, HG_SMEM);

    void* p;
    cudaGetSymbolAddress(&p, d_hb16);   unsigned short* hb16 = (unsigned short*)p;
    cudaGetSymbolAddress(&p, d_a16);    unsigned short* a16 = (unsigned short*)p;
    cudaGetSymbolAddress(&p, d_cnt);    int* cnt = (int*)p;
    cudaGetSymbolAddress(&p, d_incl);   int* incl = (int*)p;
    cudaGetSymbolAddress(&p, d_bsums);  int* bsums = (int*)p;
    cudaGetSymbolAddress(&p, d_rowptr); int* rowptr = (int*)p;
    cudaGetSymbolAddress(&p, d_wp);     uint4* wp = (uint4*)p;

    const int TPB = 256;
    int gN  = (NN + TPB - 1) / TPB;
    int gE  = (NE + TPB - 1) / TPB;
    int gW  = (NN * 32 + TPB - 1) / TPB;
    int nbN = (NN + 1023) / 1024;                 // 98
    int gFGC = gE + 3 + (NG + 1 + TPB - 1) / TPB; // fill + convW + gstart blocks
    int nT  = (NN + 127) / 128;

    // preprocessing (12 launches total in pipeline)
    k_zero_detect<<<gN, TPB>>>((const int*)ei, (const int*)batch);
    k_count_deg<<<gE, TPB>>>(ei);
    k_scan_block<<<nbN, 1024>>>(cnt, incl, bsums, NN);
    k_scan_final<<<nbN, 1024>>>(cnt, incl, bsums, rowptr, NN, nbN);
    k_fill_gstart_convW<<<gFGC, TPB>>>(ei, batch, W2, W3, W4, gE);

    // layer 1 (fused aggregate + transform)
    k_layer1<<<gW, TPB>>>(x, W1, b1);

    // layers 2-4: persistent HMMA gemm then aggregate
    k_hgemm<<<HG_GRID, 256, HG_SMEM>>>(a16, wp, hb16, nT);
    k_aggregate<<<gW, TPB>>>(hb16, b2);
    k_hgemm<<<HG_GRID, 256, HG_SMEM>>>(a16, wp + 4096, hb16, nT);
    k_aggregate<<<gW, TPB>>>(hb16, b3);
    k_hgemm<<<HG_GRID, 256, HG_SMEM>>>(a16, wp + 2 * 4096, hb16, nT);
    k_aggregate<<<gW, TPB>>>(hb16, b4);

    // pool + fc (reads bf16 a16)
    k_pool_fc<<<NG, HIDD>>>(a16, Wfc, bfc, out);
}